// round 1
// baseline (speedup 1.0000x reference)
#include <cuda_runtime.h>

#define DEGREE 20

// Rescaled Clenshaw evaluation of sum_k W_k * P_k(x), then * (1 - x^2).
//
// Standard Clenshaw for Legendre (P_{k+1} = A_k x P_k + B_k P_{k-1},
// A_k=(2k+1)/(k+1), B_k=-k/(k+1)):
//   b_k = c_k + A_k x b_{k+1} + B_{k+1} b_{k+2},  S = b_0.
// Substituting b_k = s_k d_k with s_{k+1} = s_k / A_k (s_0 = 1) makes the
// x-term coefficient exactly 1:
//   d_k = cp_k + x d_{k+1} + g_k d_{k+2},  S = d_0
// where cp_k = c_k * M_k,  M_k = prod_{j<k} A_j = C(2k,k)/2^k,
//       g_k  = -(k+1)^2 / ((2k+1)(2k+3))   (compile-time immediate).
// Inner step = 1 FFMA-imm (rt 1) + 1 FFMA 3-reg (rt 2) per degree.

__device__ __forceinline__ float legendre_eval(float xx, const float* __restrict__ cp) {
    float d1 = 0.0f, d2 = 0.0f;
#pragma unroll
    for (int k = DEGREE; k >= 0; --k) {
        // g folds to a float immediate after full unroll (all-literal expr).
        float g = -(float)((k + 1) * (k + 1)) / (float)((2 * k + 1) * (2 * k + 3));
        float u = fmaf(g, d2, cp[k]);
        float d0 = fmaf(xx, d1, u);
        d2 = d1;
        d1 = d0;
    }
    float bc = fmaf(-xx, xx, 1.0f);  // 1 - x^2
    return d1 * bc;
}

__global__ __launch_bounds__(256) void legendre_kernel(
    const float* __restrict__ x, const float* __restrict__ W,
    float* __restrict__ out, int n)
{
    // Prologue (per thread, amortized over many elements):
    // cp[k] = W[k] * M_k with M_k = prod_{j=1..k} (2j-1)/j.
    float cp[DEGREE + 1];
    {
        float M = 1.0f;
        cp[0] = __ldg(&W[0]);
#pragma unroll
        for (int k = 1; k <= DEGREE; ++k) {
            M *= (float)(2 * k - 1) / (float)k;  // ratio folds to immediate
            cp[k] = __ldg(&W[k]) * M;
        }
    }

    const int tid = blockIdx.x * blockDim.x + threadIdx.x;
    const int stride = gridDim.x * blockDim.x;
    const int n4 = n >> 2;

    const float4* __restrict__ x4 = (const float4*)x;
    float4* __restrict__ o4 = (float4*)out;

    for (int i = tid; i < n4; i += stride) {
        float4 v = x4[i];
        float4 r;
        r.x = legendre_eval(v.x, cp);
        r.y = legendre_eval(v.y, cp);
        r.z = legendre_eval(v.z, cp);
        r.w = legendre_eval(v.w, cp);
        o4[i] = r;
    }

    // Scalar tail (n % 4 != 0) — not hit for n = 8,000,000 but kept correct.
    for (int i = (n4 << 2) + tid; i < n; i += stride) {
        out[i] = legendre_eval(x[i], cp);
    }
}

extern "C" void kernel_launch(void* const* d_in, const int* in_sizes, int n_in,
                              void* d_out, int out_size) {
    const float* x = (const float*)d_in[0];
    const float* W = (const float*)d_in[1];
    // Defensive: identify W by its size (DEGREE+1 elements).
    if (n_in >= 2 && in_sizes[0] == DEGREE + 1) {
        x = (const float*)d_in[1];
        W = (const float*)d_in[0];
    }
    float* out = (float*)d_out;
    int n = out_size;

    // Grid-stride: ~6 blocks/SM on 148 SMs; each thread handles ~11 float4s,
    // amortizing the 42-op coefficient prologue.
    legendre_kernel<<<888, 256>>>(x, W, out, n);
}